// round 10
// baseline (speedup 1.0000x reference)
#include <cuda_runtime.h>
#include <cuda_fp16.h>
#include <stdint.h>

#define NMAX 100000
#define EMAX 1600000

// ---------------- scratch (static device globals) ----------------
__device__ __align__(16) float  g_q  [(size_t)NMAX * 128];
// interleaved kv: per node 256 halves = [k0..3 | v0..3 | k4..7 | v4..7 | ...]
__device__ __align__(16) __half g_kv [(size_t)NMAX * 256];
__device__ __align__(16) float  g_agg[(size_t)NMAX * 128];
__device__ __align__(16) float  g_h  [(size_t)NMAX * 128];
__device__ __align__(16) float  g_hn [(size_t)NMAX * 128];
__device__ __align__(16) float  g_t2 [(size_t)NMAX * 64];
// CSR
__device__ int    g_deg[NMAX];
__device__ int    g_rowptr[NMAX + 1];
__device__ int    g_cursor[NMAX];
__device__ int    g_esrc[EMAX];
__device__ __align__(8) float2 g_eea[EMAX];

__device__ __forceinline__ int clampi(int v, int hi) {
    return v < 0 ? 0 : (v >= hi ? hi - 1 : v);
}
__device__ __forceinline__ uint32_t f2tf32(float f) {
    uint32_t u;
    asm("cvt.rna.tf32.f32 %0, %1;" : "=r"(u) : "f"(f));
    return u;
}
__device__ __forceinline__ void mma_tf32(float4& c, const uint32_t a[4], const uint32_t b[2]) {
    asm("mma.sync.aligned.m16n8k8.row.col.f32.tf32.tf32.f32 "
        "{%0,%1,%2,%3}, {%4,%5,%6,%7}, {%8,%9}, {%0,%1,%2,%3};"
        : "+f"(c.x), "+f"(c.y), "+f"(c.z), "+f"(c.w)
        : "r"(a[0]), "r"(a[1]), "r"(a[2]), "r"(a[3]), "r"(b[0]), "r"(b[1]));
}

// ---------------- CSR build ----------------
__global__ void zero_deg(int n) {
    int i = blockIdx.x * blockDim.x + threadIdx.x;
    if (i < n) g_deg[i] = 0;
}
__global__ void hist_kernel(const int* __restrict__ ei, int E, int n) {
    int e = blockIdx.x * blockDim.x + threadIdx.x;
    if (e < E) atomicAdd(&g_deg[clampi(ei[E + e], n)], 1);
}
__global__ __launch_bounds__(1024)
void scan_kernel(int n) {
    __shared__ int sh[1024];
    int t = threadIdx.x;
    int chunk = (n + 1023) >> 10;
    int b = t * chunk;
    int e = min(n, b + chunk);
    int s = 0;
    for (int i = b; i < e; ++i) s += g_deg[i];
    sh[t] = s;
    __syncthreads();
    for (int off = 1; off < 1024; off <<= 1) {
        int v = (t >= off) ? sh[t - off] : 0;
        __syncthreads();
        sh[t] += v;
        __syncthreads();
    }
    int base = (t == 0) ? 0 : sh[t - 1];
    for (int i = b; i < e; ++i) {
        int d = g_deg[i];
        g_rowptr[i] = base;
        g_cursor[i] = base;
        base += d;
    }
    if (t == 1023) g_rowptr[n] = sh[1023];
}
__global__ void scatter_kernel(const int* __restrict__ ei, const float* __restrict__ ea,
                               int E, int n) {
    int e = blockIdx.x * blockDim.x + threadIdx.x;
    if (e >= E) return;
    int src = clampi(ei[e], n);
    int dst = clampi(ei[E + e], n);
    int pos = atomicAdd(&g_cursor[dst], 1);
    g_esrc[pos] = src;
    g_eea[pos]  = *reinterpret_cast<const float2*>(ea + (size_t)e * 2);
}

// ---------------- tf32 tensor-core GEMM, K=128, M-tile=128, N-tile=NT ----------------
template<int NT, int EPI>
__global__ __launch_bounds__(256)
void gemm_tf32(const float* __restrict__ A, const float* __restrict__ B,
               const float* __restrict__ bias, const float* __restrict__ resid,
               float* __restrict__ C, __half* __restrict__ Hkv, int M, int NCOLS)
{
    constexpr int WM = (NT == 128) ? 2 : 4;
    constexpr int WN = 8 / WM;
    constexpr int MFRAG = 8 / WM;
    constexpr int NFRAG = NT / (WN * 8);

    __shared__ uint32_t As[128][20];
    __shared__ uint32_t Bs[16][NT + 8];

    const int t = threadIdx.x;
    const int lane = t & 31;
    const int wid  = t >> 5;
    const int warp_m = wid / WN;
    const int warp_n = wid % WN;
    const int m0 = blockIdx.x * 128;
    const int n0 = blockIdx.y * NT;
    const int lr = lane >> 2, lc = lane & 3;

    float4 acc[MFRAG][NFRAG];
#pragma unroll
    for (int i = 0; i < MFRAG; ++i)
#pragma unroll
        for (int j = 0; j < NFRAG; ++j) acc[i][j] = make_float4(0.f, 0.f, 0.f, 0.f);

    const int arow = t >> 1;
    const int acb  = (t & 1) * 8;
    int agr = m0 + arow; if (agr >= M) agr = M - 1;
    const float* Ap = A + (size_t)agr * 128 + acb;

    const int brow = t >> 4;
    const int bcb  = (t & 15) * (NT / 16);
    const float* Bp = B + (size_t)brow * NCOLS + n0 + bcb;

    for (int k0 = 0; k0 < 128; k0 += 16) {
        float4 av0 = *reinterpret_cast<const float4*>(Ap + k0);
        float4 av1 = *reinterpret_cast<const float4*>(Ap + k0 + 4);
        As[arow][acb + 0] = f2tf32(av0.x); As[arow][acb + 1] = f2tf32(av0.y);
        As[arow][acb + 2] = f2tf32(av0.z); As[arow][acb + 3] = f2tf32(av0.w);
        As[arow][acb + 4] = f2tf32(av1.x); As[arow][acb + 5] = f2tf32(av1.y);
        As[arow][acb + 6] = f2tf32(av1.z); As[arow][acb + 7] = f2tf32(av1.w);
#pragma unroll
        for (int j = 0; j < NT / 64; ++j) {
            float4 bv = *reinterpret_cast<const float4*>(Bp + (size_t)k0 * NCOLS + j * 4);
            Bs[brow][bcb + j * 4 + 0] = f2tf32(bv.x);
            Bs[brow][bcb + j * 4 + 1] = f2tf32(bv.y);
            Bs[brow][bcb + j * 4 + 2] = f2tf32(bv.z);
            Bs[brow][bcb + j * 4 + 3] = f2tf32(bv.w);
        }
        __syncthreads();

#pragma unroll
        for (int ks = 0; ks < 16; ks += 8) {
            uint32_t afr[MFRAG][4];
#pragma unroll
            for (int fm = 0; fm < MFRAG; ++fm) {
                int mr = warp_m * (MFRAG * 16) + fm * 16 + lr;
                afr[fm][0] = As[mr][ks + lc];
                afr[fm][1] = As[mr + 8][ks + lc];
                afr[fm][2] = As[mr][ks + lc + 4];
                afr[fm][3] = As[mr + 8][ks + lc + 4];
            }
            uint32_t bfr[NFRAG][2];
#pragma unroll
            for (int fn = 0; fn < NFRAG; ++fn) {
                int nc = warp_n * (NFRAG * 8) + fn * 8 + lr;
                bfr[fn][0] = Bs[ks + lc][nc];
                bfr[fn][1] = Bs[ks + lc + 4][nc];
            }
#pragma unroll
            for (int fm = 0; fm < MFRAG; ++fm)
#pragma unroll
                for (int fn = 0; fn < NFRAG; ++fn)
                    mma_tf32(acc[fm][fn], afr[fm], bfr[fn]);
        }
        __syncthreads();
    }

    const int plane = n0 >> 7;
#pragma unroll
    for (int fm = 0; fm < MFRAG; ++fm) {
        int r0 = m0 + warp_m * (MFRAG * 16) + fm * 16 + lr;
        int r1 = r0 + 8;
#pragma unroll
        for (int fn = 0; fn < NFRAG; ++fn) {
            int cl = warp_n * (NFRAG * 8) + fn * 8 + 2 * lc;
            float4 c = acc[fm][fn];
            if (EPI == 0) {
                if (plane == 0) {
                    if (r0 < M) *reinterpret_cast<float2*>(C + (size_t)r0 * 128 + cl) = make_float2(c.x, c.y);
                    if (r1 < M) *reinterpret_cast<float2*>(C + (size_t)r1 * 128 + cl) = make_float2(c.z, c.w);
                } else {
                    int hi = ((cl >> 2) << 3) + (cl & 3) + ((plane == 2) ? 4 : 0);
                    if (r0 < M) *reinterpret_cast<__half2*>(Hkv + (size_t)r0 * 256 + hi) = __floats2half2_rn(c.x, c.y);
                    if (r1 < M) *reinterpret_cast<__half2*>(Hkv + (size_t)r1 * 256 + hi) = __floats2half2_rn(c.z, c.w);
                }
            } else {
                int col = n0 + cl;
                float b0 = bias[col], b1 = bias[col + 1];
                if (EPI == 1) {
                    if (r0 < M) {
                        float2 rr = *reinterpret_cast<const float2*>(resid + (size_t)r0 * NCOLS + col);
                        *reinterpret_cast<float2*>(C + (size_t)r0 * NCOLS + col) =
                            make_float2(c.x + b0 + rr.x, c.y + b1 + rr.y);
                    }
                    if (r1 < M) {
                        float2 rr = *reinterpret_cast<const float2*>(resid + (size_t)r1 * NCOLS + col);
                        *reinterpret_cast<float2*>(C + (size_t)r1 * NCOLS + col) =
                            make_float2(c.z + b0 + rr.x, c.w + b1 + rr.y);
                    }
                } else {
                    if (r0 < M)
                        *reinterpret_cast<float2*>(C + (size_t)r0 * NCOLS + col) =
                            make_float2(fmaxf(c.x + b0, 0.f), fmaxf(c.y + b1, 0.f));
                    if (r1 < M)
                        *reinterpret_cast<float2*>(C + (size_t)r1 * NCOLS + col) =
                            make_float2(fmaxf(c.z + b0, 0.f), fmaxf(c.w + b1, 0.f));
                }
            }
        }
    }
}

// ---------------- fused CSR attention: cp.async double-buffered pipeline ----------------
// 1 warp/node, EPW=8; chunk c+1 prefetched via LDGSTS while chunk c is processed from smem.
__global__ __launch_bounds__(128)
void fused_attn(const float* __restrict__ Wedge, int n)
{
    constexpr int EPW = 8;
    __shared__ __align__(16) uint8_t kvbuf[4][2][EPW][512];   // 32 KB

    int warp = threadIdx.x >> 5;
    int lane = threadIdx.x & 31;
    int i = blockIdx.x * 4 + warp;
    if (i >= n) return;
    int hg = lane >> 2;

    int beg = g_rowptr[i];
    int end = g_rowptr[i + 1];

    float4 q4 = *reinterpret_cast<const float4*>(g_q + (size_t)i * 128 + lane * 4);
    q4.x *= 0.25f; q4.y *= 0.25f; q4.z *= 0.25f; q4.w *= 0.25f;
    float w0 = Wedge[hg], w1 = Wedge[8 + hg];

    float4 accv = {0.f, 0.f, 0.f, 0.f};
    float  accd = 0.f;

#define STAGE(BUF, SB, J0) do {                                                    \
    _Pragma("unroll")                                                              \
    for (int u = 0; u < EPW; ++u) {                                                \
        int jj = min((J0) + u, end - 1);                                           \
        int idx = __ldg(g_esrc + jj);                                              \
        float2 ea2 = g_eea[jj];                                                    \
        SB[u] = ea2.x * w0 + ea2.y * w1;                                           \
        const __half* gp = g_kv + (size_t)idx * 256 + lane * 8;                    \
        uint32_t sa = (uint32_t)__cvta_generic_to_shared(                          \
            &kvbuf[warp][BUF][u][lane * 16]);                                      \
        asm volatile("cp.async.cg.shared.global [%0], [%1], 16;"                   \
                     :: "r"(sa), "l"(gp));                                         \
    }                                                                              \
    asm volatile("cp.async.commit_group;" ::: "memory");                           \
} while (0)

#define PROCESS(BUF, SB, J0) do {                                                  \
    _Pragma("unroll")                                                              \
    for (int u = 0; u < EPW; ++u) {                                                \
        uint4 kvr = *reinterpret_cast<const uint4*>(&kvbuf[warp][BUF][u][lane*16]);\
        float2 ka = __half22float2(*reinterpret_cast<const __half2*>(&kvr.x));     \
        float2 kb = __half22float2(*reinterpret_cast<const __half2*>(&kvr.y));     \
        float p = q4.x * ka.x + q4.y * ka.y + q4.z * kb.x + q4.w * kb.y;           \
        p += __shfl_xor_sync(0xffffffffu, p, 1);                                   \
        p += __shfl_xor_sync(0xffffffffu, p, 2);                                   \
        float e = __expf(p + SB[u]);                                               \
        e = ((J0) + u < end) ? e : 0.f;                                            \
        accd += e;                                                                 \
        float2 va = __half22float2(*reinterpret_cast<const __half2*>(&kvr.z));     \
        float2 vb = __half22float2(*reinterpret_cast<const __half2*>(&kvr.w));     \
        accv.x += e * va.x; accv.y += e * va.y;                                    \
        accv.z += e * vb.x; accv.w += e * vb.y;                                    \
    }                                                                              \
} while (0)

    if (beg < end) {
        float sbA[EPW], sbB[EPW];
        int j = beg;
        STAGE(0, sbA, j);
        while (true) {
            int jn = j + EPW;
            if (jn < end) {
                STAGE(1, sbB, jn);
                asm volatile("cp.async.wait_group 1;" ::: "memory");
            } else {
                asm volatile("cp.async.wait_group 0;" ::: "memory");
            }
            PROCESS(0, sbA, j);
            j = jn;
            if (j >= end) break;
            jn = j + EPW;
            if (jn < end) {
                STAGE(0, sbA, jn);
                asm volatile("cp.async.wait_group 1;" ::: "memory");
            } else {
                asm volatile("cp.async.wait_group 0;" ::: "memory");
            }
            PROCESS(1, sbB, j);
            j = jn;
            if (j >= end) break;
        }
    }
#undef STAGE
#undef PROCESS

    float invd = __fdividef(1.f, accd + 1e-16f);
    float4 o = {accv.x * invd, accv.y * invd, accv.z * invd, accv.w * invd};
    *reinterpret_cast<float4*>(g_agg + (size_t)i * 128 + lane * 4) = o;
}

// ---------------- layernorm ----------------
__global__ __launch_bounds__(256)
void ln_kernel(const float* __restrict__ lw, const float* __restrict__ lb, int n)
{
    int node = (blockIdx.x * blockDim.x + threadIdx.x) >> 5;
    int lane = threadIdx.x & 31;
    if (node >= n) return;

    float4 v = *reinterpret_cast<const float4*>(g_h + (size_t)node * 128 + lane * 4);
    float s = v.x + v.y + v.z + v.w;
    float q = v.x * v.x + v.y * v.y + v.z * v.z + v.w * v.w;
#pragma unroll
    for (int o = 16; o; o >>= 1) {
        s += __shfl_xor_sync(0xffffffffu, s, o);
        q += __shfl_xor_sync(0xffffffffu, q, o);
    }
    float mu  = s * (1.f / 128.f);
    float var = q * (1.f / 128.f) - mu * mu;
    float rs  = rsqrtf(var + 1e-5f);
    float4 w4 = *reinterpret_cast<const float4*>(lw + lane * 4);
    float4 b4 = *reinterpret_cast<const float4*>(lb + lane * 4);
    float4 o;
    o.x = (v.x - mu) * rs * w4.x + b4.x;
    o.y = (v.y - mu) * rs * w4.y + b4.y;
    o.z = (v.z - mu) * rs * w4.z + b4.z;
    o.w = (v.w - mu) * rs * w4.w + b4.w;
    *reinterpret_cast<float4*>(g_hn + (size_t)node * 128 + lane * 4) = o;
}

// ---------------- final: out[N,3] = t2[N,64] @ Wc2[64,3] + bc2 ----------------
__global__ __launch_bounds__(256)
void final_kernel(const float* __restrict__ Wc2, const float* __restrict__ bc2,
                  float* __restrict__ out, int n)
{
    int node = (blockIdx.x * blockDim.x + threadIdx.x) >> 5;
    int lane = threadIdx.x & 31;
    if (node >= n) return;

    float2 tv = *reinterpret_cast<const float2*>(g_t2 + (size_t)node * 64 + lane * 2);
    int k0 = lane * 2;
    float s0 = tv.x * Wc2[k0 * 3 + 0] + tv.y * Wc2[k0 * 3 + 3];
    float s1 = tv.x * Wc2[k0 * 3 + 1] + tv.y * Wc2[k0 * 3 + 4];
    float s2 = tv.x * Wc2[k0 * 3 + 2] + tv.y * Wc2[k0 * 3 + 5];
#pragma unroll
    for (int o = 16; o; o >>= 1) {
        s0 += __shfl_xor_sync(0xffffffffu, s0, o);
        s1 += __shfl_xor_sync(0xffffffffu, s1, o);
        s2 += __shfl_xor_sync(0xffffffffu, s2, o);
    }
    if (lane == 0) {
        out[(size_t)node * 3 + 0] = s0 + bc2[0];
        out[(size_t)node * 3 + 1] = s1 + bc2[1];
        out[(size_t)node * 3 + 2] = s2 + bc2[2];
    }
}

// ---------------- launch ----------------
extern "C" void kernel_launch(void* const* d_in, const int* in_sizes, int n_in,
                              void* d_out, int out_size)
{
    const float* x     = (const float*)d_in[0];
    const int*   ei    = (const int*)d_in[1];
    const float* ea    = (const float*)d_in[2];
    const float* Wqkv  = (const float*)d_in[3];
    const float* Wedge = (const float*)d_in[4];
    const float* Wout  = (const float*)d_in[5];
    const float* bout  = (const float*)d_in[6];
    const float* lnw   = (const float*)d_in[7];
    const float* lnb   = (const float*)d_in[8];
    const float* Wc1   = (const float*)d_in[9];
    const float* bc1   = (const float*)d_in[10];
    const float* Wc2   = (const float*)d_in[11];
    const float* bc2   = (const float*)d_in[12];
    float* out = (float*)d_out;

    const int n = in_sizes[0] / 128;
    const int E = in_sizes[1] / 2;

    float *q, *agg, *h, *hn, *t2;
    __half* kv;
    cudaGetSymbolAddress((void**)&q,   g_q);
    cudaGetSymbolAddress((void**)&kv,  g_kv);
    cudaGetSymbolAddress((void**)&agg, g_agg);
    cudaGetSymbolAddress((void**)&h,   g_h);
    cudaGetSymbolAddress((void**)&hn,  g_hn);
    cudaGetSymbolAddress((void**)&t2,  g_t2);

    // side stream + events, created once on the (uncaptured) correctness call
    static cudaStream_t s_side = nullptr;
    static cudaEvent_t ev_fork = nullptr, ev_join = nullptr;
    if (!s_side) {
        cudaStreamCreateWithFlags(&s_side, cudaStreamNonBlocking);
        cudaEventCreateWithFlags(&ev_fork, cudaEventDisableTiming);
        cudaEventCreateWithFlags(&ev_join, cudaEventDisableTiming);
    }

    // fork: CSR build on side stream, qkv GEMM on main stream
    cudaEventRecord(ev_fork, 0);
    cudaStreamWaitEvent(s_side, ev_fork, 0);

    zero_deg<<<(n + 255) / 256, 256, 0, s_side>>>(n);
    hist_kernel<<<(E + 255) / 256, 256, 0, s_side>>>(ei, E, n);
    scan_kernel<<<1, 1024, 0, s_side>>>(n);
    scatter_kernel<<<(E + 255) / 256, 256, 0, s_side>>>(ei, ea, E, n);
    cudaEventRecord(ev_join, s_side);

    // main stream: qkv = x @ Wqkv -> q fp32 plane + interleaved kv fp16
    gemm_tf32<128, 0><<<dim3((n + 127) / 128, 3), 256>>>(
        x, Wqkv, nullptr, nullptr, q, kv, n, 384);

    // join, then fused attention (needs both qkv and CSR)
    cudaStreamWaitEvent(0, ev_join, 0);
    fused_attn<<<(n + 3) / 4, 128>>>(Wedge, n);

    // h = agg @ Wout + bout + x
    gemm_tf32<128, 1><<<dim3((n + 127) / 128, 1), 256>>>(
        agg, Wout, bout, x, h, nullptr, n, 128);

    // layernorm
    ln_kernel<<<(n + 7) / 8, 256>>>(lnw, lnb, n);

    // t2 = relu(hn @ Wc1 + bc1)
    gemm_tf32<64, 2><<<dim3((n + 127) / 128, 1), 256>>>(
        hn, Wc1, bc1, nullptr, t2, nullptr, n, 64);

    // out = t2 @ Wc2 + bc2
    final_kernel<<<(n + 7) / 8, 256>>>(Wc2, bc2, out, n);
}

// round 11
// speedup vs baseline: 1.0066x; 1.0066x over previous
#include <cuda_runtime.h>
#include <cuda_fp16.h>
#include <stdint.h>

#define NMAX 100000
#define EMAX 1600000

// ---------------- scratch (static device globals) ----------------
__device__ __align__(16) float  g_q  [(size_t)NMAX * 128];
// interleaved kv: per node 256 halves = [k0..3 | v0..3 | k4..7 | v4..7 | ...]
__device__ __align__(16) __half g_kv [(size_t)NMAX * 256];
__device__ __align__(16) float  g_agg[(size_t)NMAX * 128];
__device__ __align__(16) float  g_h  [(size_t)NMAX * 128];
__device__ __align__(16) float  g_hn [(size_t)NMAX * 128];
__device__ __align__(16) float  g_t2 [(size_t)NMAX * 64];
// CSR
__device__ int    g_deg[NMAX];
__device__ int    g_rowptr[NMAX + 1];
__device__ int    g_cursor[NMAX];
__device__ int    g_esrc[EMAX];
__device__ __align__(8) float2 g_eea[EMAX];

__device__ __forceinline__ int clampi(int v, int hi) {
    return v < 0 ? 0 : (v >= hi ? hi - 1 : v);
}
__device__ __forceinline__ uint32_t f2tf32(float f) {
    uint32_t u;
    asm("cvt.rna.tf32.f32 %0, %1;" : "=r"(u) : "f"(f));
    return u;
}
__device__ __forceinline__ void mma_tf32(float4& c, const uint32_t a[4], const uint32_t b[2]) {
    asm("mma.sync.aligned.m16n8k8.row.col.f32.tf32.tf32.f32 "
        "{%0,%1,%2,%3}, {%4,%5,%6,%7}, {%8,%9}, {%0,%1,%2,%3};"
        : "+f"(c.x), "+f"(c.y), "+f"(c.z), "+f"(c.w)
        : "r"(a[0]), "r"(a[1]), "r"(a[2]), "r"(a[3]), "r"(b[0]), "r"(b[1]));
}

// ---------------- CSR build ----------------
__global__ void zero_deg(int n) {
    int i = blockIdx.x * blockDim.x + threadIdx.x;
    if (i < n) g_deg[i] = 0;
}
__global__ void hist_kernel(const int* __restrict__ ei, int E, int n) {
    int e = blockIdx.x * blockDim.x + threadIdx.x;
    if (e < E) atomicAdd(&g_deg[clampi(ei[E + e], n)], 1);
}
__global__ __launch_bounds__(1024)
void scan_kernel(int n) {
    __shared__ int sh[1024];
    int t = threadIdx.x;
    int chunk = (n + 1023) >> 10;
    int b = t * chunk;
    int e = min(n, b + chunk);
    int s = 0;
    for (int i = b; i < e; ++i) s += g_deg[i];
    sh[t] = s;
    __syncthreads();
    for (int off = 1; off < 1024; off <<= 1) {
        int v = (t >= off) ? sh[t - off] : 0;
        __syncthreads();
        sh[t] += v;
        __syncthreads();
    }
    int base = (t == 0) ? 0 : sh[t - 1];
    for (int i = b; i < e; ++i) {
        int d = g_deg[i];
        g_rowptr[i] = base;
        g_cursor[i] = base;
        base += d;
    }
    if (t == 1023) g_rowptr[n] = sh[1023];
}
__global__ void scatter_kernel(const int* __restrict__ ei, const float* __restrict__ ea,
                               int E, int n) {
    int e = blockIdx.x * blockDim.x + threadIdx.x;
    if (e >= E) return;
    int src = clampi(ei[e], n);
    int dst = clampi(ei[E + e], n);
    int pos = atomicAdd(&g_cursor[dst], 1);
    g_esrc[pos] = src;
    g_eea[pos]  = *reinterpret_cast<const float2*>(ea + (size_t)e * 2);
}

// ---------------- tf32 tensor-core GEMM, K=128, M-tile=128, N-tile=NT ----------------
template<int NT, int EPI>
__global__ __launch_bounds__(256)
void gemm_tf32(const float* __restrict__ A, const float* __restrict__ B,
               const float* __restrict__ bias, const float* __restrict__ resid,
               float* __restrict__ C, __half* __restrict__ Hkv, int M, int NCOLS)
{
    constexpr int WM = (NT == 128) ? 2 : 4;
    constexpr int WN = 8 / WM;
    constexpr int MFRAG = 8 / WM;
    constexpr int NFRAG = NT / (WN * 8);

    __shared__ uint32_t As[128][20];
    __shared__ uint32_t Bs[16][NT + 8];

    const int t = threadIdx.x;
    const int lane = t & 31;
    const int wid  = t >> 5;
    const int warp_m = wid / WN;
    const int warp_n = wid % WN;
    const int m0 = blockIdx.x * 128;
    const int n0 = blockIdx.y * NT;
    const int lr = lane >> 2, lc = lane & 3;

    float4 acc[MFRAG][NFRAG];
#pragma unroll
    for (int i = 0; i < MFRAG; ++i)
#pragma unroll
        for (int j = 0; j < NFRAG; ++j) acc[i][j] = make_float4(0.f, 0.f, 0.f, 0.f);

    const int arow = t >> 1;
    const int acb  = (t & 1) * 8;
    int agr = m0 + arow; if (agr >= M) agr = M - 1;
    const float* Ap = A + (size_t)agr * 128 + acb;

    const int brow = t >> 4;
    const int bcb  = (t & 15) * (NT / 16);
    const float* Bp = B + (size_t)brow * NCOLS + n0 + bcb;

    for (int k0 = 0; k0 < 128; k0 += 16) {
        float4 av0 = *reinterpret_cast<const float4*>(Ap + k0);
        float4 av1 = *reinterpret_cast<const float4*>(Ap + k0 + 4);
        As[arow][acb + 0] = f2tf32(av0.x); As[arow][acb + 1] = f2tf32(av0.y);
        As[arow][acb + 2] = f2tf32(av0.z); As[arow][acb + 3] = f2tf32(av0.w);
        As[arow][acb + 4] = f2tf32(av1.x); As[arow][acb + 5] = f2tf32(av1.y);
        As[arow][acb + 6] = f2tf32(av1.z); As[arow][acb + 7] = f2tf32(av1.w);
#pragma unroll
        for (int j = 0; j < NT / 64; ++j) {
            float4 bv = *reinterpret_cast<const float4*>(Bp + (size_t)k0 * NCOLS + j * 4);
            Bs[brow][bcb + j * 4 + 0] = f2tf32(bv.x);
            Bs[brow][bcb + j * 4 + 1] = f2tf32(bv.y);
            Bs[brow][bcb + j * 4 + 2] = f2tf32(bv.z);
            Bs[brow][bcb + j * 4 + 3] = f2tf32(bv.w);
        }
        __syncthreads();

#pragma unroll
        for (int ks = 0; ks < 16; ks += 8) {
            uint32_t afr[MFRAG][4];
#pragma unroll
            for (int fm = 0; fm < MFRAG; ++fm) {
                int mr = warp_m * (MFRAG * 16) + fm * 16 + lr;
                afr[fm][0] = As[mr][ks + lc];
                afr[fm][1] = As[mr + 8][ks + lc];
                afr[fm][2] = As[mr][ks + lc + 4];
                afr[fm][3] = As[mr + 8][ks + lc + 4];
            }
            uint32_t bfr[NFRAG][2];
#pragma unroll
            for (int fn = 0; fn < NFRAG; ++fn) {
                int nc = warp_n * (NFRAG * 8) + fn * 8 + lr;
                bfr[fn][0] = Bs[ks + lc][nc];
                bfr[fn][1] = Bs[ks + lc + 4][nc];
            }
#pragma unroll
            for (int fm = 0; fm < MFRAG; ++fm)
#pragma unroll
                for (int fn = 0; fn < NFRAG; ++fn)
                    mma_tf32(acc[fm][fn], afr[fm], bfr[fn]);
        }
        __syncthreads();
    }

    const int plane = n0 >> 7;
#pragma unroll
    for (int fm = 0; fm < MFRAG; ++fm) {
        int r0 = m0 + warp_m * (MFRAG * 16) + fm * 16 + lr;
        int r1 = r0 + 8;
#pragma unroll
        for (int fn = 0; fn < NFRAG; ++fn) {
            int cl = warp_n * (NFRAG * 8) + fn * 8 + 2 * lc;
            float4 c = acc[fm][fn];
            if (EPI == 0) {
                if (plane == 0) {
                    if (r0 < M) *reinterpret_cast<float2*>(C + (size_t)r0 * 128 + cl) = make_float2(c.x, c.y);
                    if (r1 < M) *reinterpret_cast<float2*>(C + (size_t)r1 * 128 + cl) = make_float2(c.z, c.w);
                } else {
                    int hi = ((cl >> 2) << 3) + (cl & 3) + ((plane == 2) ? 4 : 0);
                    if (r0 < M) *reinterpret_cast<__half2*>(Hkv + (size_t)r0 * 256 + hi) = __floats2half2_rn(c.x, c.y);
                    if (r1 < M) *reinterpret_cast<__half2*>(Hkv + (size_t)r1 * 256 + hi) = __floats2half2_rn(c.z, c.w);
                }
            } else {
                int col = n0 + cl;
                float b0 = bias[col], b1 = bias[col + 1];
                if (EPI == 1) {
                    if (r0 < M) {
                        float2 rr = *reinterpret_cast<const float2*>(resid + (size_t)r0 * NCOLS + col);
                        *reinterpret_cast<float2*>(C + (size_t)r0 * NCOLS + col) =
                            make_float2(c.x + b0 + rr.x, c.y + b1 + rr.y);
                    }
                    if (r1 < M) {
                        float2 rr = *reinterpret_cast<const float2*>(resid + (size_t)r1 * NCOLS + col);
                        *reinterpret_cast<float2*>(C + (size_t)r1 * NCOLS + col) =
                            make_float2(c.z + b0 + rr.x, c.w + b1 + rr.y);
                    }
                } else {
                    if (r0 < M)
                        *reinterpret_cast<float2*>(C + (size_t)r0 * NCOLS + col) =
                            make_float2(fmaxf(c.x + b0, 0.f), fmaxf(c.y + b1, 0.f));
                    if (r1 < M)
                        *reinterpret_cast<float2*>(C + (size_t)r1 * NCOLS + col) =
                            make_float2(fmaxf(c.z + b0, 0.f), fmaxf(c.w + b1, 0.f));
                }
            }
        }
    }
}

// ---------------- fused CSR attention: 1 warp/node, EPW=8, ONE LDG.128 per edge ----------------
__global__ __launch_bounds__(128)
void fused_attn(const float* __restrict__ Wedge, int n)
{
    constexpr int EPW = 8;
    int i    = (blockIdx.x * blockDim.x + threadIdx.x) >> 5;
    int lane = threadIdx.x & 31;
    if (i >= n) return;
    int hg = lane >> 2;

    int beg = g_rowptr[i];
    int end = g_rowptr[i + 1];

    float4 q4 = *reinterpret_cast<const float4*>(g_q + (size_t)i * 128 + lane * 4);
    q4.x *= 0.25f; q4.y *= 0.25f; q4.z *= 0.25f; q4.w *= 0.25f;
    float w0 = Wedge[hg], w1 = Wedge[8 + hg];

    float4 accv = {0.f, 0.f, 0.f, 0.f};
    float  accd = 0.f;

    for (int j = beg; j < end; j += EPW) {
        int   idx[EPW];
        float sb[EPW];
#pragma unroll
        for (int u = 0; u < EPW; ++u) {
            int jj = min(j + u, end - 1);
            idx[u] = __ldg(g_esrc + jj);
            float2 ea2 = g_eea[jj];
            sb[u] = ea2.x * w0 + ea2.y * w1;
        }
        // ONE fully-coalesced 16B load per edge per lane (k 8B + v 8B interleaved)
        uint4 kv[EPW];
#pragma unroll
        for (int u = 0; u < EPW; ++u)
            kv[u] = *reinterpret_cast<const uint4*>(g_kv + (size_t)idx[u] * 256 + lane * 8);

        float ex[EPW];
#pragma unroll
        for (int u = 0; u < EPW; ++u) {
            float2 ka = __half22float2(*reinterpret_cast<const __half2*>(&kv[u].x));
            float2 kb = __half22float2(*reinterpret_cast<const __half2*>(&kv[u].y));
            float p = q4.x * ka.x + q4.y * ka.y + q4.z * kb.x + q4.w * kb.y;
            p += __shfl_xor_sync(0xffffffffu, p, 1);
            p += __shfl_xor_sync(0xffffffffu, p, 2);
            float e = __expf(p + sb[u]);
            ex[u] = (j + u < end) ? e : 0.f;
            accd += ex[u];
        }
#pragma unroll
        for (int u = 0; u < EPW; ++u) {
            float2 va = __half22float2(*reinterpret_cast<const __half2*>(&kv[u].z));
            float2 vb = __half22float2(*reinterpret_cast<const __half2*>(&kv[u].w));
            accv.x += ex[u] * va.x;
            accv.y += ex[u] * va.y;
            accv.z += ex[u] * vb.x;
            accv.w += ex[u] * vb.y;
        }
    }

    float invd = __fdividef(1.f, accd + 1e-16f);
    float4 o = {accv.x * invd, accv.y * invd, accv.z * invd, accv.w * invd};
    *reinterpret_cast<float4*>(g_agg + (size_t)i * 128 + lane * 4) = o;
}

// ---------------- layernorm ----------------
__global__ __launch_bounds__(256)
void ln_kernel(const float* __restrict__ lw, const float* __restrict__ lb, int n)
{
    int node = (blockIdx.x * blockDim.x + threadIdx.x) >> 5;
    int lane = threadIdx.x & 31;
    if (node >= n) return;

    float4 v = *reinterpret_cast<const float4*>(g_h + (size_t)node * 128 + lane * 4);
    float s = v.x + v.y + v.z + v.w;
    float q = v.x * v.x + v.y * v.y + v.z * v.z + v.w * v.w;
#pragma unroll
    for (int o = 16; o; o >>= 1) {
        s += __shfl_xor_sync(0xffffffffu, s, o);
        q += __shfl_xor_sync(0xffffffffu, q, o);
    }
    float mu  = s * (1.f / 128.f);
    float var = q * (1.f / 128.f) - mu * mu;
    float rs  = rsqrtf(var + 1e-5f);
    float4 w4 = *reinterpret_cast<const float4*>(lw + lane * 4);
    float4 b4 = *reinterpret_cast<const float4*>(lb + lane * 4);
    float4 o;
    o.x = (v.x - mu) * rs * w4.x + b4.x;
    o.y = (v.y - mu) * rs * w4.y + b4.y;
    o.z = (v.z - mu) * rs * w4.z + b4.z;
    o.w = (v.w - mu) * rs * w4.w + b4.w;
    *reinterpret_cast<float4*>(g_hn + (size_t)node * 128 + lane * 4) = o;
}

// ---------------- final: out[N,3] = t2[N,64] @ Wc2[64,3] + bc2 ----------------
__global__ __launch_bounds__(256)
void final_kernel(const float* __restrict__ Wc2, const float* __restrict__ bc2,
                  float* __restrict__ out, int n)
{
    int node = (blockIdx.x * blockDim.x + threadIdx.x) >> 5;
    int lane = threadIdx.x & 31;
    if (node >= n) return;

    float2 tv = *reinterpret_cast<const float2*>(g_t2 + (size_t)node * 64 + lane * 2);
    int k0 = lane * 2;
    float s0 = tv.x * Wc2[k0 * 3 + 0] + tv.y * Wc2[k0 * 3 + 3];
    float s1 = tv.x * Wc2[k0 * 3 + 1] + tv.y * Wc2[k0 * 3 + 4];
    float s2 = tv.x * Wc2[k0 * 3 + 2] + tv.y * Wc2[k0 * 3 + 5];
#pragma unroll
    for (int o = 16; o; o >>= 1) {
        s0 += __shfl_xor_sync(0xffffffffu, s0, o);
        s1 += __shfl_xor_sync(0xffffffffu, s1, o);
        s2 += __shfl_xor_sync(0xffffffffu, s2, o);
    }
    if (lane == 0) {
        out[(size_t)node * 3 + 0] = s0 + bc2[0];
        out[(size_t)node * 3 + 1] = s1 + bc2[1];
        out[(size_t)node * 3 + 2] = s2 + bc2[2];
    }
}

// ---------------- launch ----------------
extern "C" void kernel_launch(void* const* d_in, const int* in_sizes, int n_in,
                              void* d_out, int out_size)
{
    const float* x     = (const float*)d_in[0];
    const int*   ei    = (const int*)d_in[1];
    const float* ea    = (const float*)d_in[2];
    const float* Wqkv  = (const float*)d_in[3];
    const float* Wedge = (const float*)d_in[4];
    const float* Wout  = (const float*)d_in[5];
    const float* bout  = (const float*)d_in[6];
    const float* lnw   = (const float*)d_in[7];
    const float* lnb   = (const float*)d_in[8];
    const float* Wc1   = (const float*)d_in[9];
    const float* bc1   = (const float*)d_in[10];
    const float* Wc2   = (const float*)d_in[11];
    const float* bc2   = (const float*)d_in[12];
    float* out = (float*)d_out;

    const int n = in_sizes[0] / 128;
    const int E = in_sizes[1] / 2;

    float *q, *agg, *h, *hn, *t2;
    __half* kv;
    cudaGetSymbolAddress((void**)&q,   g_q);
    cudaGetSymbolAddress((void**)&kv,  g_kv);
    cudaGetSymbolAddress((void**)&agg, g_agg);
    cudaGetSymbolAddress((void**)&h,   g_h);
    cudaGetSymbolAddress((void**)&hn,  g_hn);
    cudaGetSymbolAddress((void**)&t2,  g_t2);

    // side stream + events, created once on the (uncaptured) correctness call
    static cudaStream_t s_side = nullptr;
    static cudaEvent_t ev_fork = nullptr, ev_join = nullptr;
    if (!s_side) {
        cudaStreamCreateWithFlags(&s_side, cudaStreamNonBlocking);
        cudaEventCreateWithFlags(&ev_fork, cudaEventDisableTiming);
        cudaEventCreateWithFlags(&ev_join, cudaEventDisableTiming);
    }

    // fork: CSR build on side stream, qkv GEMM on main stream
    cudaEventRecord(ev_fork, 0);
    cudaStreamWaitEvent(s_side, ev_fork, 0);

    zero_deg<<<(n + 255) / 256, 256, 0, s_side>>>(n);
    hist_kernel<<<(E + 255) / 256, 256, 0, s_side>>>(ei, E, n);
    scan_kernel<<<1, 1024, 0, s_side>>>(n);
    scatter_kernel<<<(E + 255) / 256, 256, 0, s_side>>>(ei, ea, E, n);
    cudaEventRecord(ev_join, s_side);

    // main stream: qkv = x @ Wqkv -> q fp32 plane + interleaved kv fp16
    gemm_tf32<128, 0><<<dim3((n + 127) / 128, 3), 256>>>(
        x, Wqkv, nullptr, nullptr, q, kv, n, 384);

    // join, then fused attention (needs both qkv and CSR)
    cudaStreamWaitEvent(0, ev_join, 0);
    fused_attn<<<(n + 3) / 4, 128>>>(Wedge, n);

    // h = agg @ Wout + bout + x
    gemm_tf32<128, 1><<<dim3((n + 127) / 128, 1), 256>>>(
        agg, Wout, bout, x, h, nullptr, n, 128);

    // layernorm
    ln_kernel<<<(n + 7) / 8, 256>>>(lnw, lnb, n);

    // t2 = relu(hn @ Wc1 + bc1)
    gemm_tf32<64, 2><<<dim3((n + 127) / 128, 1), 256>>>(
        hn, Wc1, bc1, nullptr, t2, nullptr, n, 64);

    // out = t2 @ Wc2 + bc2
    final_kernel<<<(n + 7) / 8, 256>>>(Wc2, bc2, out, n);
}

// round 12
// speedup vs baseline: 1.0344x; 1.0276x over previous
#include <cuda_runtime.h>
#include <cuda_fp16.h>
#include <stdint.h>

#define NMAX 100000
#define EMAX 1600000

// ---------------- scratch (static device globals) ----------------
__device__ __align__(16) float  g_q  [(size_t)NMAX * 128];
// interleaved kv: per node 256 halves = [k0..3 | v0..3 | k4..7 | v4..7 | ...]
__device__ __align__(16) __half g_kv [(size_t)NMAX * 256];
__device__ __align__(16) float  g_agg[(size_t)NMAX * 128];
__device__ __align__(16) float  g_h  [(size_t)NMAX * 128];
__device__ __align__(16) float  g_hn [(size_t)NMAX * 128];
__device__ __align__(16) float  g_t2 [(size_t)NMAX * 64];
// CSR   (g_deg is zeroed by scatter_kernel for the NEXT replay; module-load zero-init
//        covers the first call — every launch sequence leaves it zeroed, so replays
//        are deterministic)
__device__ int    g_deg[NMAX];
__device__ int    g_rowptr[NMAX + 1];
__device__ int    g_cursor[NMAX];
__device__ int    g_esrc[EMAX];
__device__ __align__(8) float2 g_eea[EMAX];

__device__ __forceinline__ int clampi(int v, int hi) {
    return v < 0 ? 0 : (v >= hi ? hi - 1 : v);
}
__device__ __forceinline__ uint32_t f2tf32(float f) {
    uint32_t u;
    asm("cvt.rna.tf32.f32 %0, %1;" : "=r"(u) : "f"(f));
    return u;
}
__device__ __forceinline__ void mma_tf32(float4& c, const uint32_t a[4], const uint32_t b[2]) {
    asm("mma.sync.aligned.m16n8k8.row.col.f32.tf32.tf32.f32 "
        "{%0,%1,%2,%3}, {%4,%5,%6,%7}, {%8,%9}, {%0,%1,%2,%3};"
        : "+f"(c.x), "+f"(c.y), "+f"(c.z), "+f"(c.w)
        : "r"(a[0]), "r"(a[1]), "r"(a[2]), "r"(a[3]), "r"(b[0]), "r"(b[1]));
}

// ---------------- CSR build ----------------
__global__ __launch_bounds__(1024)
void scan_kernel(int n) {
    __shared__ int sh[1024];
    int t = threadIdx.x;
    int chunk = (n + 1023) >> 10;
    int b = t * chunk;
    int e = min(n, b + chunk);
    int s = 0;
    for (int i = b; i < e; ++i) s += g_deg[i];
    sh[t] = s;
    __syncthreads();
    for (int off = 1; off < 1024; off <<= 1) {
        int v = (t >= off) ? sh[t - off] : 0;
        __syncthreads();
        sh[t] += v;
        __syncthreads();
    }
    int base = (t == 0) ? 0 : sh[t - 1];
    for (int i = b; i < e; ++i) {
        int d = g_deg[i];
        g_rowptr[i] = base;
        g_cursor[i] = base;
        base += d;
    }
    if (t == 1023) g_rowptr[n] = sh[1023];
}
// scatter + re-zero g_deg for the next replay (scan has already consumed it)
__global__ void scatter_kernel(const int* __restrict__ ei, const float* __restrict__ ea,
                               int E, int n) {
    int e = blockIdx.x * blockDim.x + threadIdx.x;
    if (e < n) g_deg[e] = 0;
    if (e >= E) return;
    int src = clampi(ei[e], n);
    int dst = clampi(ei[E + e], n);
    int pos = atomicAdd(&g_cursor[dst], 1);
    g_esrc[pos] = src;
    g_eea[pos]  = *reinterpret_cast<const float2*>(ea + (size_t)e * 2);
}

// ---------------- tf32 tensor-core GEMM, K=128, M-tile=128, N-tile=NT ----------------
// EPI 0: qkv split -> q fp32 plane + interleaved kv fp16; blockIdx.y==3 runs the
//        edge histogram (memory-light atomics overlapped with tensor-heavy GEMM blocks)
// EPI 1: bias + resid -> C (NCOLS=128)
// EPI 2: bias + relu  -> C (NCOLS=64, NT=64)
template<int NT, int EPI>
__global__ __launch_bounds__(256)
void gemm_tf32(const float* __restrict__ A, const float* __restrict__ B,
               const float* __restrict__ bias, const float* __restrict__ resid,
               float* __restrict__ C, __half* __restrict__ Hkv, int M, int NCOLS,
               const int* __restrict__ ei, int E)
{
    if (EPI == 0 && blockIdx.y == 3) {
        // fused histogram slice
        int stride = gridDim.x * blockDim.x;
        for (int e = blockIdx.x * blockDim.x + threadIdx.x; e < E; e += stride)
            atomicAdd(&g_deg[clampi(__ldg(ei + E + e), M)], 1);
        return;
    }

    constexpr int WM = (NT == 128) ? 2 : 4;
    constexpr int WN = 8 / WM;
    constexpr int MFRAG = 8 / WM;
    constexpr int NFRAG = NT / (WN * 8);

    __shared__ uint32_t As[128][20];
    __shared__ uint32_t Bs[16][NT + 8];

    const int t = threadIdx.x;
    const int lane = t & 31;
    const int wid  = t >> 5;
    const int warp_m = wid / WN;
    const int warp_n = wid % WN;
    const int m0 = blockIdx.x * 128;
    const int n0 = blockIdx.y * NT;
    const int lr = lane >> 2, lc = lane & 3;

    float4 acc[MFRAG][NFRAG];
#pragma unroll
    for (int i = 0; i < MFRAG; ++i)
#pragma unroll
        for (int j = 0; j < NFRAG; ++j) acc[i][j] = make_float4(0.f, 0.f, 0.f, 0.f);

    const int arow = t >> 1;
    const int acb  = (t & 1) * 8;
    int agr = m0 + arow; if (agr >= M) agr = M - 1;
    const float* Ap = A + (size_t)agr * 128 + acb;

    const int brow = t >> 4;
    const int bcb  = (t & 15) * (NT / 16);
    const float* Bp = B + (size_t)brow * NCOLS + n0 + bcb;

    for (int k0 = 0; k0 < 128; k0 += 16) {
        float4 av0 = *reinterpret_cast<const float4*>(Ap + k0);
        float4 av1 = *reinterpret_cast<const float4*>(Ap + k0 + 4);
        As[arow][acb + 0] = f2tf32(av0.x); As[arow][acb + 1] = f2tf32(av0.y);
        As[arow][acb + 2] = f2tf32(av0.z); As[arow][acb + 3] = f2tf32(av0.w);
        As[arow][acb + 4] = f2tf32(av1.x); As[arow][acb + 5] = f2tf32(av1.y);
        As[arow][acb + 6] = f2tf32(av1.z); As[arow][acb + 7] = f2tf32(av1.w);
#pragma unroll
        for (int j = 0; j < NT / 64; ++j) {
            float4 bv = *reinterpret_cast<const float4*>(Bp + (size_t)k0 * NCOLS + j * 4);
            Bs[brow][bcb + j * 4 + 0] = f2tf32(bv.x);
            Bs[brow][bcb + j * 4 + 1] = f2tf32(bv.y);
            Bs[brow][bcb + j * 4 + 2] = f2tf32(bv.z);
            Bs[brow][bcb + j * 4 + 3] = f2tf32(bv.w);
        }
        __syncthreads();

#pragma unroll
        for (int ks = 0; ks < 16; ks += 8) {
            uint32_t afr[MFRAG][4];
#pragma unroll
            for (int fm = 0; fm < MFRAG; ++fm) {
                int mr = warp_m * (MFRAG * 16) + fm * 16 + lr;
                afr[fm][0] = As[mr][ks + lc];
                afr[fm][1] = As[mr + 8][ks + lc];
                afr[fm][2] = As[mr][ks + lc + 4];
                afr[fm][3] = As[mr + 8][ks + lc + 4];
            }
            uint32_t bfr[NFRAG][2];
#pragma unroll
            for (int fn = 0; fn < NFRAG; ++fn) {
                int nc = warp_n * (NFRAG * 8) + fn * 8 + lr;
                bfr[fn][0] = Bs[ks + lc][nc];
                bfr[fn][1] = Bs[ks + lc + 4][nc];
            }
#pragma unroll
            for (int fm = 0; fm < MFRAG; ++fm)
#pragma unroll
                for (int fn = 0; fn < NFRAG; ++fn)
                    mma_tf32(acc[fm][fn], afr[fm], bfr[fn]);
        }
        __syncthreads();
    }

    const int plane = n0 >> 7;
#pragma unroll
    for (int fm = 0; fm < MFRAG; ++fm) {
        int r0 = m0 + warp_m * (MFRAG * 16) + fm * 16 + lr;
        int r1 = r0 + 8;
#pragma unroll
        for (int fn = 0; fn < NFRAG; ++fn) {
            int cl = warp_n * (NFRAG * 8) + fn * 8 + 2 * lc;
            float4 c = acc[fm][fn];
            if (EPI == 0) {
                if (plane == 0) {
                    if (r0 < M) *reinterpret_cast<float2*>(C + (size_t)r0 * 128 + cl) = make_float2(c.x, c.y);
                    if (r1 < M) *reinterpret_cast<float2*>(C + (size_t)r1 * 128 + cl) = make_float2(c.z, c.w);
                } else {
                    int hi = ((cl >> 2) << 3) + (cl & 3) + ((plane == 2) ? 4 : 0);
                    if (r0 < M) *reinterpret_cast<__half2*>(Hkv + (size_t)r0 * 256 + hi) = __floats2half2_rn(c.x, c.y);
                    if (r1 < M) *reinterpret_cast<__half2*>(Hkv + (size_t)r1 * 256 + hi) = __floats2half2_rn(c.z, c.w);
                }
            } else {
                int col = n0 + cl;
                float b0 = bias[col], b1 = bias[col + 1];
                if (EPI == 1) {
                    if (r0 < M) {
                        float2 rr = *reinterpret_cast<const float2*>(resid + (size_t)r0 * NCOLS + col);
                        *reinterpret_cast<float2*>(C + (size_t)r0 * NCOLS + col) =
                            make_float2(c.x + b0 + rr.x, c.y + b1 + rr.y);
                    }
                    if (r1 < M) {
                        float2 rr = *reinterpret_cast<const float2*>(resid + (size_t)r1 * NCOLS + col);
                        *reinterpret_cast<float2*>(C + (size_t)r1 * NCOLS + col) =
                            make_float2(c.z + b0 + rr.x, c.w + b1 + rr.y);
                    }
                } else {
                    if (r0 < M)
                        *reinterpret_cast<float2*>(C + (size_t)r0 * NCOLS + col) =
                            make_float2(fmaxf(c.x + b0, 0.f), fmaxf(c.y + b1, 0.f));
                    if (r1 < M)
                        *reinterpret_cast<float2*>(C + (size_t)r1 * NCOLS + col) =
                            make_float2(fmaxf(c.z + b0, 0.f), fmaxf(c.w + b1, 0.f));
                }
            }
        }
    }
}

// ---------------- fused CSR attention: 1 warp/node, EPW=8, ONE LDG.128 per edge ----------------
__global__ __launch_bounds__(128)
void fused_attn(const float* __restrict__ Wedge, int n)
{
    constexpr int EPW = 8;
    int i    = (blockIdx.x * blockDim.x + threadIdx.x) >> 5;
    int lane = threadIdx.x & 31;
    if (i >= n) return;
    int hg = lane >> 2;

    int beg = g_rowptr[i];
    int end = g_rowptr[i + 1];

    float4 q4 = *reinterpret_cast<const float4*>(g_q + (size_t)i * 128 + lane * 4);
    q4.x *= 0.25f; q4.y *= 0.25f; q4.z *= 0.25f; q4.w *= 0.25f;
    float w0 = Wedge[hg], w1 = Wedge[8 + hg];

    float4 accv = {0.f, 0.f, 0.f, 0.f};
    float  accd = 0.f;

    for (int j = beg; j < end; j += EPW) {
        int   idx[EPW];
        float sb[EPW];
#pragma unroll
        for (int u = 0; u < EPW; ++u) {
            int jj = min(j + u, end - 1);
            idx[u] = __ldg(g_esrc + jj);
            float2 ea2 = g_eea[jj];
            sb[u] = ea2.x * w0 + ea2.y * w1;
        }
        uint4 kv[EPW];
#pragma unroll
        for (int u = 0; u < EPW; ++u)
            kv[u] = *reinterpret_cast<const uint4*>(g_kv + (size_t)idx[u] * 256 + lane * 8);

        float ex[EPW];
#pragma unroll
        for (int u = 0; u < EPW; ++u) {
            float2 ka = __half22float2(*reinterpret_cast<const __half2*>(&kv[u].x));
            float2 kb = __half22float2(*reinterpret_cast<const __half2*>(&kv[u].y));
            float p = q4.x * ka.x + q4.y * ka.y + q4.z * kb.x + q4.w * kb.y;
            p += __shfl_xor_sync(0xffffffffu, p, 1);
            p += __shfl_xor_sync(0xffffffffu, p, 2);
            float e = __expf(p + sb[u]);
            ex[u] = (j + u < end) ? e : 0.f;
            accd += ex[u];
        }
#pragma unroll
        for (int u = 0; u < EPW; ++u) {
            float2 va = __half22float2(*reinterpret_cast<const __half2*>(&kv[u].z));
            float2 vb = __half22float2(*reinterpret_cast<const __half2*>(&kv[u].w));
            accv.x += ex[u] * va.x;
            accv.y += ex[u] * va.y;
            accv.z += ex[u] * vb.x;
            accv.w += ex[u] * vb.y;
        }
    }

    float invd = __fdividef(1.f, accd + 1e-16f);
    float4 o = {accv.x * invd, accv.y * invd, accv.z * invd, accv.w * invd};
    *reinterpret_cast<float4*>(g_agg + (size_t)i * 128 + lane * 4) = o;
}

// ---------------- layernorm ----------------
__global__ __launch_bounds__(256)
void ln_kernel(const float* __restrict__ lw, const float* __restrict__ lb, int n)
{
    int node = (blockIdx.x * blockDim.x + threadIdx.x) >> 5;
    int lane = threadIdx.x & 31;
    if (node >= n) return;

    float4 v = *reinterpret_cast<const float4*>(g_h + (size_t)node * 128 + lane * 4);
    float s = v.x + v.y + v.z + v.w;
    float q = v.x * v.x + v.y * v.y + v.z * v.z + v.w * v.w;
#pragma unroll
    for (int o = 16; o; o >>= 1) {
        s += __shfl_xor_sync(0xffffffffu, s, o);
        q += __shfl_xor_sync(0xffffffffu, q, o);
    }
    float mu  = s * (1.f / 128.f);
    float var = q * (1.f / 128.f) - mu * mu;
    float rs  = rsqrtf(var + 1e-5f);
    float4 w4 = *reinterpret_cast<const float4*>(lw + lane * 4);
    float4 b4 = *reinterpret_cast<const float4*>(lb + lane * 4);
    float4 o;
    o.x = (v.x - mu) * rs * w4.x + b4.x;
    o.y = (v.y - mu) * rs * w4.y + b4.y;
    o.z = (v.z - mu) * rs * w4.z + b4.z;
    o.w = (v.w - mu) * rs * w4.w + b4.w;
    *reinterpret_cast<float4*>(g_hn + (size_t)node * 128 + lane * 4) = o;
}

// ---------------- final: out[N,3] = t2[N,64] @ Wc2[64,3] + bc2 ----------------
__global__ __launch_bounds__(256)
void final_kernel(const float* __restrict__ Wc2, const float* __restrict__ bc2,
                  float* __restrict__ out, int n)
{
    int node = (blockIdx.x * blockDim.x + threadIdx.x) >> 5;
    int lane = threadIdx.x & 31;
    if (node >= n) return;

    float2 tv = *reinterpret_cast<const float2*>(g_t2 + (size_t)node * 64 + lane * 2);
    int k0 = lane * 2;
    float s0 = tv.x * Wc2[k0 * 3 + 0] + tv.y * Wc2[k0 * 3 + 3];
    float s1 = tv.x * Wc2[k0 * 3 + 1] + tv.y * Wc2[k0 * 3 + 4];
    float s2 = tv.x * Wc2[k0 * 3 + 2] + tv.y * Wc2[k0 * 3 + 5];
#pragma unroll
    for (int o = 16; o; o >>= 1) {
        s0 += __shfl_xor_sync(0xffffffffu, s0, o);
        s1 += __shfl_xor_sync(0xffffffffu, s1, o);
        s2 += __shfl_xor_sync(0xffffffffu, s2, o);
    }
    if (lane == 0) {
        out[(size_t)node * 3 + 0] = s0 + bc2[0];
        out[(size_t)node * 3 + 1] = s1 + bc2[1];
        out[(size_t)node * 3 + 2] = s2 + bc2[2];
    }
}

// ---------------- launch ----------------
extern "C" void kernel_launch(void* const* d_in, const int* in_sizes, int n_in,
                              void* d_out, int out_size)
{
    const float* x     = (const float*)d_in[0];
    const int*   ei    = (const int*)d_in[1];
    const float* ea    = (const float*)d_in[2];
    const float* Wqkv  = (const float*)d_in[3];
    const float* Wedge = (const float*)d_in[4];
    const float* Wout  = (const float*)d_in[5];
    const float* bout  = (const float*)d_in[6];
    const float* lnw   = (const float*)d_in[7];
    const float* lnb   = (const float*)d_in[8];
    const float* Wc1   = (const float*)d_in[9];
    const float* bc1   = (const float*)d_in[10];
    const float* Wc2   = (const float*)d_in[11];
    const float* bc2   = (const float*)d_in[12];
    float* out = (float*)d_out;

    const int n = in_sizes[0] / 128;
    const int E = in_sizes[1] / 2;

    float *q, *agg, *h, *hn, *t2;
    __half* kv;
    cudaGetSymbolAddress((void**)&q,   g_q);
    cudaGetSymbolAddress((void**)&kv,  g_kv);
    cudaGetSymbolAddress((void**)&agg, g_agg);
    cudaGetSymbolAddress((void**)&h,   g_h);
    cudaGetSymbolAddress((void**)&hn,  g_hn);
    cudaGetSymbolAddress((void**)&t2,  g_t2);

    // 1. qkv = x @ Wqkv -> q fp32 + interleaved kv fp16; y==3 slice = edge histogram
    gemm_tf32<128, 0><<<dim3((n + 127) / 128, 4), 256>>>(
        x, Wqkv, nullptr, nullptr, q, kv, n, 384, ei, E);

    // 2. exclusive scan -> rowptr/cursor
    scan_kernel<<<1, 1024>>>(n);

    // 3. scatter edges into CSR (+ re-zero g_deg for next replay)
    scatter_kernel<<<(E + 255) / 256, 256>>>(ei, ea, E, n);

    // 4. fused per-node attention   <-- profiled slot
    fused_attn<<<(n + 3) / 4, 128>>>(Wedge, n);

    // 5. h = agg @ Wout + bout + x
    gemm_tf32<128, 1><<<dim3((n + 127) / 128, 1), 256>>>(
        agg, Wout, bout, x, h, nullptr, n, 128, nullptr, 0);

    // 6. layernorm
    ln_kernel<<<(n + 7) / 8, 256>>>(lnw, lnb, n);

    // 7. t2 = relu(hn @ Wc1 + bc1)
    gemm_tf32<64, 2><<<dim3((n + 127) / 128, 1), 256>>>(
        hn, Wc1, bc1, nullptr, t2, nullptr, n, 64, nullptr, 0);

    // 8. out = t2 @ Wc2 + bc2
    final_kernel<<<(n + 7) / 8, 256>>>(Wc2, bc2, out, n);
}